// round 16
// baseline (speedup 1.0000x reference)
#include <cuda_runtime.h>
#include <cuda_fp16.h>
#include <cuda_bf16.h>
#include <cstdint>

// ---------------------------------------------------------------------------
// HiPPO-LegT: chunked convolution + one big GEMM.
// Main GEMM: mma.sync fp16 single limb (Ah*Bh, fp32 acc) + causal skips.
// Pow chain: tensor-core 3-limb bf16 with PERSISTED limb panels (R15).
// Combine: 3-launch Kogge-Stone scan, device-derived pointers (R14, proven).
// b_limbs + s fused into one launch (R14, proven).  15 launches total.
// ---------------------------------------------------------------------------

#define N_ST   256
#define T_CH   128
#define MAT    65536
#define NCHUNK 6
#define AB_BLK 16384              // bytes: 128 rows x 64 k fp16 (swizzled)
#define BB_BLK 32768              // bytes: 256 rows x 64 k fp16 (swizzled)

// main mma kernel smem: per stage [Ah 16K][B 32K], 3 stages
#define ST_B   16384
#define ST_SZ  49152
#define NSTG   3
#define SMEM_SZ (NSTG * ST_SZ)

// pow kernel smem: 2 stages x [Ph 16K][Pl 16K][Rh 16K][Rl 16K]
#define PWS_PL 16384
#define PWS_RH 32768
#define PWS_RL 49152
#define PWS_SZ 65536
#define PW_SMEM (2 * PWS_SZ)

// limb-panel layout: matrix 256x256 bf16 as 8 panels of 16KB:
//   panel = (row>>7)*4 + (col>>6); inner swz((row&127)*128 + (col&63)*2)
#define LIMB_BYTES 131072         // per power per limb (8 panels x 16KB)

#define HSZ    (512 * 256)        // one chunk-state block

// ---- device scratch ----
__device__ __align__(256) float g_Apow[129 * MAT];     // fp32 A^1..A^128
__device__ __align__(256) __half2 g_LH[(size_t)129 * LIMB_BYTES / 4]; // hi limbs
__device__ __align__(256) __half2 g_LL[(size_t)129 * LIMB_BYTES / 4]; // lo limbs
__device__ __align__(256) float g_V[T_CH * N_ST];
__device__ __align__(256) float g_Q2[MAT];             // (A^128)^2
__device__ __align__(256) float g_Q4[MAT];             // (A^128)^4
__device__ __align__(256) float g_S[8 * HSZ];
__device__ __align__(256) float g_H[8 * HSZ];
__device__ __align__(256) __half g_Ah[(size_t)32 * NCHUNK * 8192];
__device__ __align__(256) __half g_Bh[(size_t)128 * NCHUNK * 16384];

// ---------------------------------------------------------------------------
__device__ __forceinline__ uint32_t smem_u32(const void* p) {
    uint32_t a;
    asm("{ .reg .u64 t; cvta.to.shared.u64 t, %1; cvt.u32.u64 %0, t; }" : "=r"(a) : "l"(p));
    return a;
}
__device__ __forceinline__ void cp16(uint32_t s, const void* g) {
    asm volatile("cp.async.cg.shared.global [%0], [%1], 16;" :: "r"(s), "l"(g));
}
#define CP_COMMIT() asm volatile("cp.async.commit_group;" ::: "memory")
#define CP_WAIT(n)  asm volatile("cp.async.wait_group %0;" :: "n"(n) : "memory")

__device__ __forceinline__ void ldm4(uint32_t* r, uint32_t addr) {
    asm volatile("ldmatrix.sync.aligned.m8n8.x4.shared.b16 {%0,%1,%2,%3}, [%4];"
                 : "=r"(r[0]), "=r"(r[1]), "=r"(r[2]), "=r"(r[3]) : "r"(addr));
}
__device__ __forceinline__ void ldm4t(uint32_t* r, uint32_t addr) {
    asm volatile("ldmatrix.sync.aligned.m8n8.x4.trans.shared.b16 {%0,%1,%2,%3}, [%4];"
                 : "=r"(r[0]), "=r"(r[1]), "=r"(r[2]), "=r"(r[3]) : "r"(addr));
}
__device__ __forceinline__ void mma16816(float* d, const uint32_t* a,
                                         uint32_t b0, uint32_t b1) {
    asm volatile(
        "mma.sync.aligned.m16n8k16.row.col.f32.f16.f16.f32 "
        "{%0,%1,%2,%3}, {%4,%5,%6,%7}, {%8,%9}, {%0,%1,%2,%3};"
        : "+f"(d[0]), "+f"(d[1]), "+f"(d[2]), "+f"(d[3])
        : "r"(a[0]), "r"(a[1]), "r"(a[2]), "r"(a[3]), "r"(b0), "r"(b1));
}
__device__ __forceinline__ void mmabf(float* d, const uint32_t* a,
                                      uint32_t b0, uint32_t b1) {
    asm volatile(
        "mma.sync.aligned.m16n8k16.row.col.f32.bf16.bf16.f32 "
        "{%0,%1,%2,%3}, {%4,%5,%6,%7}, {%8,%9}, {%0,%1,%2,%3};"
        : "+f"(d[0]), "+f"(d[1]), "+f"(d[2]), "+f"(d[3])
        : "r"(a[0]), "r"(a[1]), "r"(a[2]), "r"(a[3]), "r"(b0), "r"(b1));
}

__device__ __forceinline__ uint32_t swz(uint32_t off) { return off ^ ((off >> 3) & 0x70); }

__device__ __forceinline__ unsigned short hbits(float x) {
    __half h = __float2half_rn(x);
    return *reinterpret_cast<unsigned short*>(&h);
}
__device__ __forceinline__ unsigned short bfb(__nv_bfloat16 b) {
    return *reinterpret_cast<unsigned short*>(&b);
}
__device__ __forceinline__ void split_bf(float x, unsigned short& h, unsigned short& l) {
    __nv_bfloat16 bh = __float2bfloat16(x);
    h = bfb(bh);
    l = bfb(__float2bfloat16(x - __bfloat162float(bh)));
}

// ---------------------------------------------------------------------------
// conv_a: A (fp32 input) -> g_Apow[1] fp32 + limb panels for power 1.
// ---------------------------------------------------------------------------
__global__ void conv_a_kernel(const float* __restrict__ A) {
    const int idx = blockIdx.x * 256 + threadIdx.x;   // 0..16383
    const int row = idx >> 6;
    const int c0 = (idx & 63) * 4;
    float4 f = *(const float4*)&A[(size_t)row * 256 + c0];
    float v[4] = {f.x, f.y, f.z, f.w};
    *(float4*)&g_Apow[(size_t)MAT + row * 256 + c0] = f;
    unsigned short h[4], l[4];
#pragma unroll
    for (int q = 0; q < 4; q++) split_bf(v[q], h[q], l[q]);
    const uint32_t panel = (uint32_t)(row >> 7) * 4 + (c0 >> 6);
    const uint32_t off = panel * 16384 + swz((uint32_t)((row & 127) * 128 + (c0 & 63) * 2));
    char* LH = (char*)g_LH + (size_t)1 * LIMB_BYTES;
    char* LL = (char*)g_LL + (size_t)1 * LIMB_BYTES;
    uint2 ph, pl;
    ph.x = (uint32_t)h[0] | ((uint32_t)h[1] << 16);
    ph.y = (uint32_t)h[2] | ((uint32_t)h[3] << 16);
    pl.x = (uint32_t)l[0] | ((uint32_t)l[1] << 16);
    pl.y = (uint32_t)l[2] | ((uint32_t)l[3] << 16);
    *(uint2*)(LH + off) = ph;
    *(uint2*)(LL + off) = pl;
}

// ---------------------------------------------------------------------------
// pow level (R15 verbatim): A^{d+j} = A^d @ A^j, limbs streamed + persisted.
// ---------------------------------------------------------------------------
__global__ __launch_bounds__(256) void pow_mma_kernel(int d) {
    extern __shared__ char smem[];
    const uint32_t sb = smem_u32(smem);
    const int tid = threadIdx.x;
    const int wid = tid >> 5, lane = tid & 31;
    const int j = blockIdx.z + 1;
    const int pw = d + j;
    const int bm = blockIdx.y * 128;
    const int bn = blockIdx.x * 128;
    const int m0w = (wid & 3) * 32;
    const int n0w = (wid >> 2) * 64;

    const char* PH = (const char*)g_LH + (size_t)d * LIMB_BYTES;
    const char* PL = (const char*)g_LL + (size_t)d * LIMB_BYTES;
    const char* RH = (const char*)g_LH + (size_t)j * LIMB_BYTES;
    const char* RL = (const char*)g_LL + (size_t)j * LIMB_BYTES;

    uint32_t aoff[2][4];
    {
        const uint32_t arow = (uint32_t)(m0w + (lane & 15)) * 128;
        const uint32_t khalf = (uint32_t)(lane >> 4) * 16;
#pragma unroll
        for (int mt = 0; mt < 2; mt++)
#pragma unroll
            for (int ks = 0; ks < 4; ks++)
                aoff[mt][ks] = swz(arow + (uint32_t)mt * 2048 + khalf + ks * 32);
    }
    uint32_t boff0[4];
    {
        const int i = lane & 7, jm = lane >> 3;
        const uint32_t kl = (uint32_t)(i + (jm & 1) * 8);
        const uint32_t nb = (uint32_t)((jm >> 1) * 8);
#pragma unroll
        for (int ng = 0; ng < 4; ng++)
            boff0[ng] = swz(kl * 128 + (uint32_t)(ng * 16 + nb) * 2);
    }
    const uint32_t rpsel = (uint32_t)(n0w >> 6) * 8192;

    float acc[2][8][4];
#pragma unroll
    for (int mt = 0; mt < 2; mt++)
#pragma unroll
        for (int nt = 0; nt < 8; nt++)
#pragma unroll
            for (int q = 0; q < 4; q++) acc[mt][nt][q] = 0.f;

    const uint32_t cpo = (uint32_t)tid * 16;   // < 4096

#define PW_LOAD(kb, st)                                                         \
    do {                                                                        \
        const uint32_t s0 = sb + (uint32_t)(st) * PWS_SZ;                       \
        const uint32_t pp = (uint32_t)((bm >> 7) * 4 + ((kb) >> 6)) * 16384;    \
        const uint32_t pr = (uint32_t)((((kb) >> 7) * 4) + (bn >> 6)) * 16384 + \
                            (uint32_t)(((kb) & 64) << 7);                       \
        _Pragma("unroll")                                                       \
        for (int q = 0; q < 4; q++) {                                           \
            cp16(s0 + q * 4096 + cpo,          PH + pp + q * 4096 + cpo);       \
            cp16(s0 + PWS_PL + q * 4096 + cpo, PL + pp + q * 4096 + cpo);       \
        }                                                                       \
        _Pragma("unroll")                                                       \
        for (int q = 0; q < 2; q++) {                                           \
            cp16(s0 + PWS_RH + q * 4096 + cpo,        RH + pr + q * 4096 + cpo);\
            cp16(s0 + PWS_RH + 8192 + q * 4096 + cpo, RH + pr + 16384 + q * 4096 + cpo);\
            cp16(s0 + PWS_RL + q * 4096 + cpo,        RL + pr + q * 4096 + cpo);\
            cp16(s0 + PWS_RL + 8192 + q * 4096 + cpo, RL + pr + 16384 + q * 4096 + cpo);\
        }                                                                       \
        CP_COMMIT();                                                            \
    } while (0)

    PW_LOAD(0, 0);
    PW_LOAD(64, 1);

    for (int cx = 0; cx < 4; cx++) {
        if (cx + 2 < 4) CP_WAIT(1); else CP_WAIT(0);
        __syncthreads();
        const uint32_t st = sb + (uint32_t)(cx & 1) * PWS_SZ;
#pragma unroll
        for (int ks = 0; ks < 4; ks++) {
            uint32_t ah[2][4], al[2][4];
#pragma unroll
            for (int mt = 0; mt < 2; mt++) {
                ldm4(ah[mt], st + aoff[mt][ks]);
                ldm4(al[mt], st + PWS_PL + aoff[mt][ks]);
            }
            const uint32_t rk = (uint32_t)ks * 2048;
#pragma unroll
            for (int ng = 0; ng < 4; ng++) {
                uint32_t bh[4], bl[4];
                ldm4t(bh, st + PWS_RH + rpsel + rk + boff0[ng]);
                ldm4t(bl, st + PWS_RL + rpsel + rk + boff0[ng]);
#pragma unroll
                for (int mt = 0; mt < 2; mt++) {
                    mmabf(acc[mt][2 * ng + 0], ah[mt], bh[0], bh[1]);
                    mmabf(acc[mt][2 * ng + 1], ah[mt], bh[2], bh[3]);
                    mmabf(acc[mt][2 * ng + 0], ah[mt], bl[0], bl[1]);
                    mmabf(acc[mt][2 * ng + 1], ah[mt], bl[2], bl[3]);
                    mmabf(acc[mt][2 * ng + 0], al[mt], bh[0], bh[1]);
                    mmabf(acc[mt][2 * ng + 1], al[mt], bh[2], bh[3]);
                }
            }
        }
        __syncthreads();
        if (cx + 2 < 4) PW_LOAD((cx + 2) * 64, cx & 1);
    }
#undef PW_LOAD

    float* C = g_Apow + (size_t)pw * MAT;
    char* LHo = (char*)g_LH + (size_t)pw * LIMB_BYTES;
    char* LLo = (char*)g_LL + (size_t)pw * LIMB_BYTES;
    const int rl0 = m0w + (lane >> 2);
    const int cl0 = n0w + (lane & 3) * 2;
#pragma unroll
    for (int mt = 0; mt < 2; mt++) {
#pragma unroll
        for (int nt = 0; nt < 8; nt++) {
            const int cl = cl0 + nt * 8;
            const int cg = bn + cl;
            const uint32_t panel = (uint32_t)((bm >> 7) * 4 + (cg >> 6)) * 16384;
            const uint32_t cin = (uint32_t)(cl & 63) * 2;
#pragma unroll
            for (int sub = 0; sub < 2; sub++) {
                const int rl = rl0 + mt * 16 + sub * 8;
                const float v0 = acc[mt][nt][sub * 2 + 0];
                const float v1 = acc[mt][nt][sub * 2 + 1];
                *(float2*)&C[(size_t)(bm + rl) * 256 + cg] = make_float2(v0, v1);
                unsigned short h0, l0, h1, l1;
                split_bf(v0, h0, l0);
                split_bf(v1, h1, l1);
                const uint32_t off = panel + swz((uint32_t)rl * 128 + cin);
                *(uint32_t*)(LHo + off) = (uint32_t)h0 | ((uint32_t)h1 << 16);
                *(uint32_t*)(LLo + off) = (uint32_t)l0 | ((uint32_t)l1 << 16);
            }
        }
    }
}

// ---------------------------------------------------------------------------
// fp32 32x32-tile GEMM bodies (R14 verbatim)
// ---------------------------------------------------------------------------
__device__ __forceinline__ void gemm32_nn(const float* __restrict__ Am,
                                          const float* __restrict__ Bm,
                                          float* __restrict__ Cm,
                                          int brow, int bcol) {
    __shared__ float As[16][33];
    __shared__ float Bs[16][33];
    const int tid = threadIdx.x;
    const int ty = tid >> 4, tx = tid & 15;
    const int ar = tid >> 3;
    const int ak = (tid & 7) * 2;
    const int bk = tid >> 4;
    const int bc = (tid & 15) * 2;
    float acc[2][2] = {};
    for (int k0 = 0; k0 < 256; k0 += 16) {
        float2 a2 = *(const float2*)&Am[(size_t)(brow + ar) * 256 + k0 + ak];
        As[ak][ar] = a2.x; As[ak + 1][ar] = a2.y;
        float2 b2 = *(const float2*)&Bm[(size_t)(k0 + bk) * 256 + bcol + bc];
        Bs[bk][bc] = b2.x; Bs[bk][bc + 1] = b2.y;
        __syncthreads();
#pragma unroll
        for (int k = 0; k < 16; k++) {
            float a0 = As[k][ty * 2], a1 = As[k][ty * 2 + 1];
            float b0 = Bs[k][tx * 2], b1 = Bs[k][tx * 2 + 1];
            acc[0][0] += a0 * b0; acc[0][1] += a0 * b1;
            acc[1][0] += a1 * b0; acc[1][1] += a1 * b1;
        }
        __syncthreads();
    }
#pragma unroll
    for (int ii = 0; ii < 2; ii++) {
        float2 v = make_float2(acc[ii][0], acc[ii][1]);
        *(float2*)&Cm[(size_t)(brow + ty * 2 + ii) * 256 + bcol + tx * 2] = v;
    }
}

__device__ __forceinline__ void gemm32_ntr(const float* __restrict__ Am,
                                           const float* __restrict__ Bt,
                                           float* __restrict__ Cm,
                                           const float* __restrict__ bias,
                                           int brow, int bcol) {
    __shared__ float As[16][33];
    __shared__ float Bs[16][33];
    const int tid = threadIdx.x;
    const int ty = tid >> 4, tx = tid & 15;
    const int ar = tid >> 3;
    const int ak = (tid & 7) * 2;
    float acc[2][2] = {};
    for (int k0 = 0; k0 < 256; k0 += 16) {
        float2 a2 = *(const float2*)&Am[(size_t)(brow + ar) * 256 + k0 + ak];
        As[ak][ar] = a2.x; As[ak + 1][ar] = a2.y;
        float2 b2 = *(const float2*)&Bt[(size_t)(bcol + ar) * 256 + k0 + ak];
        Bs[ak][ar] = b2.x; Bs[ak + 1][ar] = b2.y;
        __syncthreads();
#pragma unroll
        for (int k = 0; k < 16; k++) {
            float a0 = As[k][ty * 2], a1 = As[k][ty * 2 + 1];
            float b0 = Bs[k][tx * 2], b1 = Bs[k][tx * 2 + 1];
            acc[0][0] += a0 * b0; acc[0][1] += a0 * b1;
            acc[1][0] += a1 * b0; acc[1][1] += a1 * b1;
        }
        __syncthreads();
    }
#pragma unroll
    for (int ii = 0; ii < 2; ii++) {
        const size_t off = (size_t)(brow + ty * 2 + ii) * 256 + bcol + tx * 2;
        float2 b = *(const float2*)&bias[off];
        float2 v = make_float2(acc[ii][0] + b.x, acc[ii][1] + b.y);
        *(float2*)&Cm[off] = v;
    }
}

// ---------------------------------------------------------------------------
// Kogge-Stone scan step (R14 verbatim — pointers derived in device code):
//   step 0: H[i] = S[i] + S[i-1] @ Q^T     (+ Q2 = Q@Q job)
//   step 1: S[i] = H[i] + H[i-2] @ Q2^T    (+ Q4 = Q2@Q2 job)
//   step 2: H[i] = S[i] + S[i-4] @ Q4^T
// ---------------------------------------------------------------------------
__global__ void scan_kernel(int step) {
    const float* in;
    float* outp;
    const float* Qp;
    int shift;
    const float* qsrc = nullptr;
    float* qdst = nullptr;
    if (step == 0) {
        in = g_S; outp = g_H; Qp = g_Apow + (size_t)128 * MAT; shift = 1;
        qsrc = Qp; qdst = g_Q2;
    } else if (step == 1) {
        in = g_H; outp = g_S; Qp = g_Q2; shift = 2;
        qsrc = g_Q2; qdst = g_Q4;
    } else {
        in = g_S; outp = g_H; Qp = g_Q4; shift = 4;
    }

    const int bid = blockIdx.x;
    if (bid < 1024) {
        const int i = bid >> 7;
        const int tile = bid & 127;
        const int brow = (tile >> 3) * 32;
        const int bcol = (tile & 7) * 32;
        const float* ini = in + (size_t)i * HSZ;
        float* outi = outp + (size_t)i * HSZ;
        if (i < shift) {   // pass-through copy
            const int rr = threadIdx.x >> 3;
            const int cc = (threadIdx.x & 7) * 4;
            *(float4*)&outi[(size_t)(brow + rr) * 256 + bcol + cc] =
                *(const float4*)&ini[(size_t)(brow + rr) * 256 + bcol + cc];
        } else {
            gemm32_ntr(in + (size_t)(i - shift) * HSZ, Qp, outi, ini, brow, bcol);
        }
    } else if (qdst) {
        const int tile = bid - 1024;
        gemm32_nn(qsrc, qsrc, qdst, (tile >> 3) * 32, (tile & 7) * 32);
    }
}

// ---------------------------------------------------------------------------
__global__ void v_kernel(const float* __restrict__ Bv) {
    __shared__ float bs[256];
    int j = blockIdx.x, n = threadIdx.x;
    bs[n] = Bv[n];
    __syncthreads();
    if (j == 0) { g_V[n] = bs[n]; return; }
    const float* Am = g_Apow + (size_t)j * MAT;
    float s = 0.f;
#pragma unroll 8
    for (int m = 0; m < 256; m++) s += Am[n * 256 + m] * bs[m];
    g_V[j * 256 + n] = s;
}

// ---------------------------------------------------------------------------
// Fused: blocks 0..767 = b_limbs (fp16 B packer); blocks 768..4863 = s jobs.
// (R14 verbatim; H[0]=S[0] is handled by scan step 0's copy path)
// ---------------------------------------------------------------------------
__global__ void bs_fused_kernel(const float* __restrict__ inp) {
    const int bid = blockIdx.x;
    const int tid = threadIdx.x;
    if (bid < 128 * NCHUNK) {
        const int t = bid / NCHUNK, kc = bid % NCHUNK;
        const int kk0 = (tid & 15) * 4;
        char* dh = (char*)g_Bh + (size_t)bid * BB_BLK;
        for (int it = 0; it < 16; it++) {
            int n = it * 16 + (tid >> 4);
            float v[4];
            if (kc < 2) {
                int k0 = kc * 64 + kk0;
#pragma unroll
                for (int q = 0; q < 4; q++) {
                    int k = k0 + q;
                    v[q] = (k <= t) ? g_V[(t - k) * 256 + n] : 0.f;
                }
            } else {
                int m0 = kc * 64 + kk0 - 128;
                float4 a4 = *(const float4*)&g_Apow[(size_t)(t + 1) * MAT +
                                                    n * 256 + m0];
                v[0] = a4.x; v[1] = a4.y; v[2] = a4.z; v[3] = a4.w;
            }
            uint2 ph;
            ph.x = (uint32_t)hbits(v[0]) | ((uint32_t)hbits(v[1]) << 16);
            ph.y = (uint32_t)hbits(v[2]) | ((uint32_t)hbits(v[3]) << 16);
            uint32_t off = swz((uint32_t)(n * 128 + kk0 * 2));
            *(uint2*)(dh + off) = ph;
        }
    } else {
        __shared__ float fs[128];
        const int sid = bid - 128 * NCHUNK;
        const int r = sid & 511, i = sid >> 9, n = tid;
        if (n < 128) fs[n] = inp[r * 1024 + i * T_CH + n];
        __syncthreads();
        float s = 0.f;
#pragma unroll 4
        for (int k = 0; k < 128; k++)
            s += g_V[(127 - k) * 256 + n] * fs[k];
        g_S[(size_t)(i * 512 + r) * 256 + n] = s;
    }
}

__global__ void a_limbs_kernel(const float* __restrict__ inp) {
    const int blk = blockIdx.x;            // rt*6 + kc
    const int rt = blk / NCHUNK, kc = blk % NCHUNK;
    const int i = rt >> 2;
    const int tid = threadIdx.x;
    const int kk0 = (tid & 15) * 4;
    char* dh = (char*)g_Ah + (size_t)blk * AB_BLK;
    for (int it = 0; it < 8; it++) {
        int row = it * 16 + (tid >> 4);
        int r = (rt & 3) * 128 + row;
        float v[4];
        if (kc < 2) {
            float4 f4 = *(const float4*)&inp[r * 1024 + i * 128 + kc * 64 + kk0];
            v[0] = f4.x; v[1] = f4.y; v[2] = f4.z; v[3] = f4.w;
        } else if (i == 0) {
            v[0] = v[1] = v[2] = v[3] = 0.f;
        } else {
            float4 f4 = *(const float4*)&g_H[(size_t)((i - 1) * 512 + r) * 256 +
                                             (kc - 2) * 64 + kk0];
            v[0] = f4.x; v[1] = f4.y; v[2] = f4.z; v[3] = f4.w;
        }
        uint2 ph;
        ph.x = (uint32_t)hbits(v[0]) | ((uint32_t)hbits(v[1]) << 16);
        ph.y = (uint32_t)hbits(v[2]) | ((uint32_t)hbits(v[3]) << 16);
        uint32_t off = swz((uint32_t)(row * 128 + kk0 * 2));
        *(uint2*)(dh + off) = ph;
    }
}

// ---------------------------------------------------------------------------
// Main GEMM (unchanged — passing since round 8)
// ---------------------------------------------------------------------------
__global__ __launch_bounds__(512, 1) void main_mma_kernel(float* __restrict__ out) {
    extern __shared__ char smem[];
    const uint32_t sb = smem_u32(smem);
    const int tid = threadIdx.x;
    const int wid = tid >> 5;
    const int lane = tid & 31;
    const int t = blockIdx.x;
    const int by = blockIdx.y;

    const int m0w = (wid & 3) * 32;
    const int n0w = (wid >> 2) * 64;

    int clist[6] = {0, 1, 2, 3, 4, 5};
    int nch = 6;
    if (t < 64) { clist[1] = 2; clist[2] = 3; clist[3] = 4; clist[4] = 5; nch = 5; }

    const int nks_c0 = min(4, (t >> 4) + 1);
    const int nks_c1 = (t < 64) ? 0 : min(4, ((t - 64) >> 4) + 1);

    const char* Asrc = (const char*)g_Ah + (size_t)by * NCHUNK * AB_BLK;
    const char* Bsrc = (const char*)g_Bh + (size_t)t * NCHUNK * BB_BLK;

    const uint32_t cpo = (uint32_t)tid * 16;

    uint32_t aoff[2][4];
    uint32_t boff[4][4];
    {
        const uint32_t arow = (uint32_t)(m0w + (lane & 15)) * 128;
        const uint32_t khalf = (uint32_t)(lane >> 4) * 16;
#pragma unroll
        for (int mt = 0; mt < 2; mt++)
#pragma unroll
            for (int ks = 0; ks < 4; ks++)
                aoff[mt][ks] = swz(arow + (uint32_t)mt * 2048 + khalf + ks * 32);
        const uint32_t brow = (uint32_t)(n0w + (lane & 15)) * 128;
#pragma unroll
        for (int ng = 0; ng < 4; ng++)
#pragma unroll
            for (int ks = 0; ks < 4; ks++)
                boff[ng][ks] = swz(brow + (uint32_t)ng * 2048 + khalf + ks * 32);
    }

    float acc[2][8][4];
#pragma unroll
    for (int mt = 0; mt < 2; mt++)
#pragma unroll
        for (int nt = 0; nt < 8; nt++)
#pragma unroll
            for (int q = 0; q < 4; q++) acc[mt][nt][q] = 0.f;

#define LOAD_STAGE(kc, st)                                                      \
    do {                                                                        \
        uint32_t s0 = sb + (uint32_t)(st) * ST_SZ;                              \
        const char* ga = Asrc + (size_t)(kc) * AB_BLK;                          \
        const char* gc = Bsrc + (size_t)(kc) * BB_BLK;                          \
        cp16(s0 + cpo, ga + cpo);                                               \
        cp16(s0 + 8192 + cpo, ga + 8192 + cpo);                                 \
        _Pragma("unroll")                                                       \
        for (int q = 0; q < 4; q++)                                             \
            cp16(s0 + ST_B + q * 8192 + cpo, gc + q * 8192 + cpo);              \
        CP_COMMIT();                                                            \
    } while (0)

    LOAD_STAGE(clist[0], 0);
    LOAD_STAGE(clist[1], 1);

    for (int j = 0; j < nch; j++) {
        if (j + NSTG - 1 < nch) {
            LOAD_STAGE(clist[j + NSTG - 1], (j + NSTG - 1) % NSTG);
            CP_WAIT(2);
        } else if (j == nch - 2) {
            CP_WAIT(1);
        } else {
            CP_WAIT(0);
        }
        __syncthreads();
        const uint32_t st = sb + (uint32_t)(j % NSTG) * ST_SZ;
        const int kc = clist[j];
        const int nks = (kc == 0) ? nks_c0 : ((kc == 1) ? nks_c1 : 4);
#pragma unroll
        for (int ks = 0; ks < 4; ks++) {
            if (ks >= nks) break;
            uint32_t ah[2][4];
            ldm4(ah[0], st + aoff[0][ks]);
            ldm4(ah[1], st + aoff[1][ks]);
#pragma unroll
            for (int ng = 0; ng < 4; ng++) {
                uint32_t bh[4];
                ldm4(bh, st + ST_B + boff[ng][ks]);
#pragma unroll
                for (int mt = 0; mt < 2; mt++) {
                    mma16816(acc[mt][2 * ng + 0], ah[mt], bh[0], bh[2]);
                    mma16816(acc[mt][2 * ng + 1], ah[mt], bh[1], bh[3]);
                }
            }
        }
        __syncthreads();
    }
#undef LOAD_STAGE

    const int i_ch = by >> 2;
    float* ob = out + (size_t)(i_ch * 128 + t) * 131072;
    const int rbase = (by & 3) * 128 + m0w + (lane >> 2);
    const int cbase = n0w + (lane & 3) * 2;
#pragma unroll
    for (int mt = 0; mt < 2; mt++) {
        const int r0 = rbase + mt * 16;
#pragma unroll
        for (int nt = 0; nt < 8; nt++) {
            const int c = cbase + nt * 8;
            float2 v0 = make_float2(acc[mt][nt][0], acc[mt][nt][1]);
            float2 v1 = make_float2(acc[mt][nt][2], acc[mt][nt][3]);
            __stcs((float2*)(ob + (size_t)r0 * 256 + c), v0);
            __stcs((float2*)(ob + (size_t)(r0 + 8) * 256 + c), v1);
        }
    }
}

// ---------------------------------------------------------------------------
extern "C" void kernel_launch(void* const* d_in, const int* in_sizes, int n_in,
                              void* d_out, int out_size) {
    const float* inp = (const float*)d_in[0];   // (8,64,1024)
    const float* A   = (const float*)d_in[1];   // (256,256)
    const float* Bv  = (const float*)d_in[2];   // (256,)
    float* out = (float*)d_out;

    cudaFuncSetAttribute(main_mma_kernel,
                         cudaFuncAttributeMaxDynamicSharedMemorySize, SMEM_SZ);
    cudaFuncSetAttribute(pow_mma_kernel,
                         cudaFuncAttributeMaxDynamicSharedMemorySize, PW_SMEM);

    conv_a_kernel<<<64, 256>>>(A);
    for (int d = 1; d <= 64; d <<= 1)
        pow_mma_kernel<<<dim3(2, 2, d), 256, PW_SMEM>>>(d);

    v_kernel<<<128, 256>>>(Bv);
    bs_fused_kernel<<<128 * NCHUNK + 4096, 256>>>(inp);

    scan_kernel<<<1088, 256>>>(0);
    scan_kernel<<<1088, 256>>>(1);
    scan_kernel<<<1024, 256>>>(2);

    a_limbs_kernel<<<32 * NCHUNK, 256>>>(inp);

    main_mma_kernel<<<dim3(128, 32), 512, SMEM_SZ>>>(out);
}

// round 17
// speedup vs baseline: 1.0391x; 1.0391x over previous
#include <cuda_runtime.h>
#include <cuda_fp16.h>
#include <cuda_bf16.h>
#include <cstdint>

// ---------------------------------------------------------------------------
// HiPPO-LegT: chunked convolution + one big GEMM.
// Main GEMM: mma.sync fp16 single limb (Ah*Bh, fp32 acc) + causal skips.
// Pow chain: tensor-core 3-limb bf16 with PERSISTED limb panels (R15).
// Combine: stride-2 Horner — tprep (T[i]=S[i-1]Q^T+S[i], +Q2 job) then 3
// pair launches H[k]=H[k-2]Q2^T+T[k].  (R15 otherwise verbatim.)
// ---------------------------------------------------------------------------

#define N_ST   256
#define T_CH   128
#define MAT    65536
#define NCHUNK 6
#define AB_BLK 16384              // bytes: 128 rows x 64 k fp16 (swizzled)
#define BB_BLK 32768              // bytes: 256 rows x 64 k fp16 (swizzled)

// main mma kernel smem: per stage [Ah 16K][B 32K], 3 stages
#define ST_B   16384
#define ST_SZ  49152
#define NSTG   3
#define SMEM_SZ (NSTG * ST_SZ)

// pow kernel smem: 2 stages x [Ph 16K][Pl 16K][Rh 16K][Rl 16K]
#define PWS_PL 16384
#define PWS_RH 32768
#define PWS_RL 49152
#define PWS_SZ 65536
#define PW_SMEM (2 * PWS_SZ)

// limb-panel layout: matrix 256x256 bf16 as 8 panels of 16KB:
//   panel = (row>>7)*4 + (col>>6); inner swz((row&127)*128 + (col&63)*2)
#define LIMB_BYTES 131072         // per power per limb (8 panels x 16KB)

#define HSZ    (512 * 256)        // one chunk-state block

// ---- device scratch ----
__device__ __align__(256) float g_Apow[129 * MAT];     // fp32 A^1..A^128
__device__ __align__(256) __half2 g_LH[(size_t)129 * LIMB_BYTES / 4]; // hi limbs
__device__ __align__(256) __half2 g_LL[(size_t)129 * LIMB_BYTES / 4]; // lo limbs
__device__ __align__(256) float g_V[T_CH * N_ST];
__device__ __align__(256) float g_Q2[MAT];             // (A^128)^2
__device__ __align__(256) float g_S[8 * HSZ];
__device__ __align__(256) float g_H[8 * HSZ];
__device__ __align__(256) __half g_Ah[(size_t)32 * NCHUNK * 8192];
__device__ __align__(256) __half g_Bh[(size_t)128 * NCHUNK * 16384];

// ---------------------------------------------------------------------------
__device__ __forceinline__ uint32_t smem_u32(const void* p) {
    uint32_t a;
    asm("{ .reg .u64 t; cvta.to.shared.u64 t, %1; cvt.u32.u64 %0, t; }" : "=r"(a) : "l"(p));
    return a;
}
__device__ __forceinline__ void cp16(uint32_t s, const void* g) {
    asm volatile("cp.async.cg.shared.global [%0], [%1], 16;" :: "r"(s), "l"(g));
}
#define CP_COMMIT() asm volatile("cp.async.commit_group;" ::: "memory")
#define CP_WAIT(n)  asm volatile("cp.async.wait_group %0;" :: "n"(n) : "memory")

__device__ __forceinline__ void ldm4(uint32_t* r, uint32_t addr) {
    asm volatile("ldmatrix.sync.aligned.m8n8.x4.shared.b16 {%0,%1,%2,%3}, [%4];"
                 : "=r"(r[0]), "=r"(r[1]), "=r"(r[2]), "=r"(r[3]) : "r"(addr));
}
__device__ __forceinline__ void ldm4t(uint32_t* r, uint32_t addr) {
    asm volatile("ldmatrix.sync.aligned.m8n8.x4.trans.shared.b16 {%0,%1,%2,%3}, [%4];"
                 : "=r"(r[0]), "=r"(r[1]), "=r"(r[2]), "=r"(r[3]) : "r"(addr));
}
__device__ __forceinline__ void mma16816(float* d, const uint32_t* a,
                                         uint32_t b0, uint32_t b1) {
    asm volatile(
        "mma.sync.aligned.m16n8k16.row.col.f32.f16.f16.f32 "
        "{%0,%1,%2,%3}, {%4,%5,%6,%7}, {%8,%9}, {%0,%1,%2,%3};"
        : "+f"(d[0]), "+f"(d[1]), "+f"(d[2]), "+f"(d[3])
        : "r"(a[0]), "r"(a[1]), "r"(a[2]), "r"(a[3]), "r"(b0), "r"(b1));
}
__device__ __forceinline__ void mmabf(float* d, const uint32_t* a,
                                      uint32_t b0, uint32_t b1) {
    asm volatile(
        "mma.sync.aligned.m16n8k16.row.col.f32.bf16.bf16.f32 "
        "{%0,%1,%2,%3}, {%4,%5,%6,%7}, {%8,%9}, {%0,%1,%2,%3};"
        : "+f"(d[0]), "+f"(d[1]), "+f"(d[2]), "+f"(d[3])
        : "r"(a[0]), "r"(a[1]), "r"(a[2]), "r"(a[3]), "r"(b0), "r"(b1));
}

__device__ __forceinline__ uint32_t swz(uint32_t off) { return off ^ ((off >> 3) & 0x70); }

__device__ __forceinline__ unsigned short hbits(float x) {
    __half h = __float2half_rn(x);
    return *reinterpret_cast<unsigned short*>(&h);
}
__device__ __forceinline__ unsigned short bfb(__nv_bfloat16 b) {
    return *reinterpret_cast<unsigned short*>(&b);
}
__device__ __forceinline__ void split_bf(float x, unsigned short& h, unsigned short& l) {
    __nv_bfloat16 bh = __float2bfloat16(x);
    h = bfb(bh);
    l = bfb(__float2bfloat16(x - __bfloat162float(bh)));
}

// ---------------------------------------------------------------------------
// conv_a: A (fp32 input) -> g_Apow[1] fp32 + limb panels for power 1.
// ---------------------------------------------------------------------------
__global__ void conv_a_kernel(const float* __restrict__ A) {
    const int idx = blockIdx.x * 256 + threadIdx.x;   // 0..16383
    const int row = idx >> 6;
    const int c0 = (idx & 63) * 4;
    float4 f = *(const float4*)&A[(size_t)row * 256 + c0];
    float v[4] = {f.x, f.y, f.z, f.w};
    *(float4*)&g_Apow[(size_t)MAT + row * 256 + c0] = f;
    unsigned short h[4], l[4];
#pragma unroll
    for (int q = 0; q < 4; q++) split_bf(v[q], h[q], l[q]);
    const uint32_t panel = (uint32_t)(row >> 7) * 4 + (c0 >> 6);
    const uint32_t off = panel * 16384 + swz((uint32_t)((row & 127) * 128 + (c0 & 63) * 2));
    char* LH = (char*)g_LH + (size_t)1 * LIMB_BYTES;
    char* LL = (char*)g_LL + (size_t)1 * LIMB_BYTES;
    uint2 ph, pl;
    ph.x = (uint32_t)h[0] | ((uint32_t)h[1] << 16);
    ph.y = (uint32_t)h[2] | ((uint32_t)h[3] << 16);
    pl.x = (uint32_t)l[0] | ((uint32_t)l[1] << 16);
    pl.y = (uint32_t)l[2] | ((uint32_t)l[3] << 16);
    *(uint2*)(LH + off) = ph;
    *(uint2*)(LL + off) = pl;
}

// ---------------------------------------------------------------------------
// pow level (R15 verbatim): A^{d+j} = A^d @ A^j, limbs streamed + persisted.
// ---------------------------------------------------------------------------
__global__ __launch_bounds__(256) void pow_mma_kernel(int d) {
    extern __shared__ char smem[];
    const uint32_t sb = smem_u32(smem);
    const int tid = threadIdx.x;
    const int wid = tid >> 5, lane = tid & 31;
    const int j = blockIdx.z + 1;
    const int pw = d + j;
    const int bm = blockIdx.y * 128;
    const int bn = blockIdx.x * 128;
    const int m0w = (wid & 3) * 32;
    const int n0w = (wid >> 2) * 64;

    const char* PH = (const char*)g_LH + (size_t)d * LIMB_BYTES;
    const char* PL = (const char*)g_LL + (size_t)d * LIMB_BYTES;
    const char* RH = (const char*)g_LH + (size_t)j * LIMB_BYTES;
    const char* RL = (const char*)g_LL + (size_t)j * LIMB_BYTES;

    uint32_t aoff[2][4];
    {
        const uint32_t arow = (uint32_t)(m0w + (lane & 15)) * 128;
        const uint32_t khalf = (uint32_t)(lane >> 4) * 16;
#pragma unroll
        for (int mt = 0; mt < 2; mt++)
#pragma unroll
            for (int ks = 0; ks < 4; ks++)
                aoff[mt][ks] = swz(arow + (uint32_t)mt * 2048 + khalf + ks * 32);
    }
    uint32_t boff0[4];
    {
        const int i = lane & 7, jm = lane >> 3;
        const uint32_t kl = (uint32_t)(i + (jm & 1) * 8);
        const uint32_t nb = (uint32_t)((jm >> 1) * 8);
#pragma unroll
        for (int ng = 0; ng < 4; ng++)
            boff0[ng] = swz(kl * 128 + (uint32_t)(ng * 16 + nb) * 2);
    }
    const uint32_t rpsel = (uint32_t)(n0w >> 6) * 8192;

    float acc[2][8][4];
#pragma unroll
    for (int mt = 0; mt < 2; mt++)
#pragma unroll
        for (int nt = 0; nt < 8; nt++)
#pragma unroll
            for (int q = 0; q < 4; q++) acc[mt][nt][q] = 0.f;

    const uint32_t cpo = (uint32_t)tid * 16;   // < 4096

#define PW_LOAD(kb, st)                                                         \
    do {                                                                        \
        const uint32_t s0 = sb + (uint32_t)(st) * PWS_SZ;                       \
        const uint32_t pp = (uint32_t)((bm >> 7) * 4 + ((kb) >> 6)) * 16384;    \
        const uint32_t pr = (uint32_t)((((kb) >> 7) * 4) + (bn >> 6)) * 16384 + \
                            (uint32_t)(((kb) & 64) << 7);                       \
        _Pragma("unroll")                                                       \
        for (int q = 0; q < 4; q++) {                                           \
            cp16(s0 + q * 4096 + cpo,          PH + pp + q * 4096 + cpo);       \
            cp16(s0 + PWS_PL + q * 4096 + cpo, PL + pp + q * 4096 + cpo);       \
        }                                                                       \
        _Pragma("unroll")                                                       \
        for (int q = 0; q < 2; q++) {                                           \
            cp16(s0 + PWS_RH + q * 4096 + cpo,        RH + pr + q * 4096 + cpo);\
            cp16(s0 + PWS_RH + 8192 + q * 4096 + cpo, RH + pr + 16384 + q * 4096 + cpo);\
            cp16(s0 + PWS_RL + q * 4096 + cpo,        RL + pr + q * 4096 + cpo);\
            cp16(s0 + PWS_RL + 8192 + q * 4096 + cpo, RL + pr + 16384 + q * 4096 + cpo);\
        }                                                                       \
        CP_COMMIT();                                                            \
    } while (0)

    PW_LOAD(0, 0);
    PW_LOAD(64, 1);

    for (int cx = 0; cx < 4; cx++) {
        if (cx + 2 < 4) CP_WAIT(1); else CP_WAIT(0);
        __syncthreads();
        const uint32_t st = sb + (uint32_t)(cx & 1) * PWS_SZ;
#pragma unroll
        for (int ks = 0; ks < 4; ks++) {
            uint32_t ah[2][4], al[2][4];
#pragma unroll
            for (int mt = 0; mt < 2; mt++) {
                ldm4(ah[mt], st + aoff[mt][ks]);
                ldm4(al[mt], st + PWS_PL + aoff[mt][ks]);
            }
            const uint32_t rk = (uint32_t)ks * 2048;
#pragma unroll
            for (int ng = 0; ng < 4; ng++) {
                uint32_t bh[4], bl[4];
                ldm4t(bh, st + PWS_RH + rpsel + rk + boff0[ng]);
                ldm4t(bl, st + PWS_RL + rpsel + rk + boff0[ng]);
#pragma unroll
                for (int mt = 0; mt < 2; mt++) {
                    mmabf(acc[mt][2 * ng + 0], ah[mt], bh[0], bh[1]);
                    mmabf(acc[mt][2 * ng + 1], ah[mt], bh[2], bh[3]);
                    mmabf(acc[mt][2 * ng + 0], ah[mt], bl[0], bl[1]);
                    mmabf(acc[mt][2 * ng + 1], ah[mt], bl[2], bl[3]);
                    mmabf(acc[mt][2 * ng + 0], al[mt], bh[0], bh[1]);
                    mmabf(acc[mt][2 * ng + 1], al[mt], bh[2], bh[3]);
                }
            }
        }
        __syncthreads();
        if (cx + 2 < 4) PW_LOAD((cx + 2) * 64, cx & 1);
    }
#undef PW_LOAD

    float* C = g_Apow + (size_t)pw * MAT;
    char* LHo = (char*)g_LH + (size_t)pw * LIMB_BYTES;
    char* LLo = (char*)g_LL + (size_t)pw * LIMB_BYTES;
    const int rl0 = m0w + (lane >> 2);
    const int cl0 = n0w + (lane & 3) * 2;
#pragma unroll
    for (int mt = 0; mt < 2; mt++) {
#pragma unroll
        for (int nt = 0; nt < 8; nt++) {
            const int cl = cl0 + nt * 8;
            const int cg = bn + cl;
            const uint32_t panel = (uint32_t)((bm >> 7) * 4 + (cg >> 6)) * 16384;
            const uint32_t cin = (uint32_t)(cl & 63) * 2;
#pragma unroll
            for (int sub = 0; sub < 2; sub++) {
                const int rl = rl0 + mt * 16 + sub * 8;
                const float v0 = acc[mt][nt][sub * 2 + 0];
                const float v1 = acc[mt][nt][sub * 2 + 1];
                *(float2*)&C[(size_t)(bm + rl) * 256 + cg] = make_float2(v0, v1);
                unsigned short h0, l0, h1, l1;
                split_bf(v0, h0, l0);
                split_bf(v1, h1, l1);
                const uint32_t off = panel + swz((uint32_t)rl * 128 + cin);
                *(uint32_t*)(LHo + off) = (uint32_t)h0 | ((uint32_t)h1 << 16);
                *(uint32_t*)(LLo + off) = (uint32_t)l0 | ((uint32_t)l1 << 16);
            }
        }
    }
}

// ---------------------------------------------------------------------------
// fp32 32x32-tile GEMM bodies
// ---------------------------------------------------------------------------
__device__ __forceinline__ void gemm32_nn(const float* __restrict__ Am,
                                          const float* __restrict__ Bm,
                                          float* __restrict__ Cm,
                                          int brow, int bcol) {
    __shared__ float As[16][33];
    __shared__ float Bs[16][33];
    const int tid = threadIdx.x;
    const int ty = tid >> 4, tx = tid & 15;
    const int ar = tid >> 3;
    const int ak = (tid & 7) * 2;
    const int bk = tid >> 4;
    const int bc = (tid & 15) * 2;
    float acc[2][2] = {};
    for (int k0 = 0; k0 < 256; k0 += 16) {
        float2 a2 = *(const float2*)&Am[(size_t)(brow + ar) * 256 + k0 + ak];
        As[ak][ar] = a2.x; As[ak + 1][ar] = a2.y;
        float2 b2 = *(const float2*)&Bm[(size_t)(k0 + bk) * 256 + bcol + bc];
        Bs[bk][bc] = b2.x; Bs[bk][bc + 1] = b2.y;
        __syncthreads();
#pragma unroll
        for (int k = 0; k < 16; k++) {
            float a0 = As[k][ty * 2], a1 = As[k][ty * 2 + 1];
            float b0 = Bs[k][tx * 2], b1 = Bs[k][tx * 2 + 1];
            acc[0][0] += a0 * b0; acc[0][1] += a0 * b1;
            acc[1][0] += a1 * b0; acc[1][1] += a1 * b1;
        }
        __syncthreads();
    }
#pragma unroll
    for (int ii = 0; ii < 2; ii++) {
        float2 v = make_float2(acc[ii][0], acc[ii][1]);
        *(float2*)&Cm[(size_t)(brow + ty * 2 + ii) * 256 + bcol + tx * 2] = v;
    }
}

__device__ __forceinline__ void gemm32_ntr(const float* __restrict__ Am,
                                           const float* __restrict__ Bt,
                                           float* __restrict__ Cm,
                                           const float* __restrict__ bias,
                                           int brow, int bcol) {
    __shared__ float As[16][33];
    __shared__ float Bs[16][33];
    const int tid = threadIdx.x;
    const int ty = tid >> 4, tx = tid & 15;
    const int ar = tid >> 3;
    const int ak = (tid & 7) * 2;
    float acc[2][2] = {};
    for (int k0 = 0; k0 < 256; k0 += 16) {
        float2 a2 = *(const float2*)&Am[(size_t)(brow + ar) * 256 + k0 + ak];
        As[ak][ar] = a2.x; As[ak + 1][ar] = a2.y;
        float2 b2 = *(const float2*)&Bt[(size_t)(bcol + ar) * 256 + k0 + ak];
        Bs[ak][ar] = b2.x; Bs[ak + 1][ar] = b2.y;
        __syncthreads();
#pragma unroll
        for (int k = 0; k < 16; k++) {
            float a0 = As[k][ty * 2], a1 = As[k][ty * 2 + 1];
            float b0 = Bs[k][tx * 2], b1 = Bs[k][tx * 2 + 1];
            acc[0][0] += a0 * b0; acc[0][1] += a0 * b1;
            acc[1][0] += a1 * b0; acc[1][1] += a1 * b1;
        }
        __syncthreads();
    }
#pragma unroll
    for (int ii = 0; ii < 2; ii++) {
        const size_t off = (size_t)(brow + ty * 2 + ii) * 256 + bcol + tx * 2;
        float2 b = *(const float2*)&bias[off];
        float2 v = make_float2(acc[ii][0] + b.x, acc[ii][1] + b.y);
        *(float2*)&Cm[off] = v;
    }
}

// ---------------------------------------------------------------------------
// Stride-2 Horner combine.
// tprep: blocks 0..767: T[i] = S[i-1]@Q^T + S[i] -> g_H[i], i = 1..6.
//        blocks 768..831: Q2 = Q@Q (64 tiles).
// pair(p): H[2p+sub] = H[2p+sub-2]@Q2^T + T[2p+sub] (in place in g_H),
//          sub = bid>>7 (p=3 has only sub=0 -> H6).
// ---------------------------------------------------------------------------
__global__ void tprep_kernel() {
    const float* Q = g_Apow + (size_t)128 * MAT;
    const int bid = blockIdx.x;
    if (bid < 768) {
        const int i = (bid >> 7) + 1;          // 1..6
        const int tile = bid & 127;
        gemm32_ntr(g_S + (size_t)(i - 1) * HSZ, Q,
                   g_H + (size_t)i * HSZ,
                   g_S + (size_t)i * HSZ,
                   (tile >> 3) * 32, (tile & 7) * 32);
    } else {
        const int tile = bid - 768;
        gemm32_nn(Q, Q, g_Q2, (tile >> 3) * 32, (tile & 7) * 32);
    }
}

__global__ void pair_kernel(int p) {
    const int bid = blockIdx.x;
    const int sub = bid >> 7;                  // 0 or 1
    const int k = 2 * p + sub;                 // 2,3 / 4,5 / 6
    const int tile = bid & 127;
    gemm32_ntr(g_H + (size_t)(k - 2) * HSZ, g_Q2,
               g_H + (size_t)k * HSZ,
               g_H + (size_t)k * HSZ,          // bias = T[k] (in place)
               (tile >> 3) * 32, (tile & 7) * 32);
}

__global__ void v_kernel(const float* __restrict__ Bv) {
    __shared__ float bs[256];
    int j = blockIdx.x, n = threadIdx.x;
    bs[n] = Bv[n];
    __syncthreads();
    if (j == 0) { g_V[n] = bs[n]; return; }
    const float* Am = g_Apow + (size_t)j * MAT;
    float s = 0.f;
#pragma unroll 8
    for (int m = 0; m < 256; m++) s += Am[n * 256 + m] * bs[m];
    g_V[j * 256 + n] = s;
}

__global__ void s_kernel(const float* __restrict__ inp) {
    __shared__ float fs[128];
    int r = blockIdx.x, i = blockIdx.y, n = threadIdx.x;
    if (n < 128) fs[n] = inp[r * 1024 + i * T_CH + n];
    __syncthreads();
    float s = 0.f;
#pragma unroll 4
    for (int k = 0; k < 128; k++)
        s += g_V[(127 - k) * 256 + n] * fs[k];
    g_S[(i * 512 + r) * 256 + n] = s;
    if (i == 0) g_H[r * 256 + n] = s;   // H[0] = S[0]
}

// ---------------------------------------------------------------------------
// packers (fp16 single limb), SW128-swizzled, exact smem image. (R15 verbatim)
// ---------------------------------------------------------------------------
__global__ void b_limbs_kernel() {
    const int blk = blockIdx.x;            // t*6 + kc
    const int t = blk / NCHUNK, kc = blk % NCHUNK;
    const int tid = threadIdx.x;
    const int kk0 = (tid & 15) * 4;
    char* dh = (char*)g_Bh + (size_t)blk * BB_BLK;
    for (int it = 0; it < 16; it++) {
        int n = it * 16 + (tid >> 4);
        float v[4];
        if (kc < 2) {
            int k0 = kc * 64 + kk0;
#pragma unroll
            for (int q = 0; q < 4; q++) {
                int k = k0 + q;
                v[q] = (k <= t) ? g_V[(t - k) * 256 + n] : 0.f;
            }
        } else {
            int m0 = kc * 64 + kk0 - 128;
            float4 a4 = *(const float4*)&g_Apow[(size_t)(t + 1) * MAT + n * 256 + m0];
            v[0] = a4.x; v[1] = a4.y; v[2] = a4.z; v[3] = a4.w;
        }
        uint2 ph;
        ph.x = (uint32_t)hbits(v[0]) | ((uint32_t)hbits(v[1]) << 16);
        ph.y = (uint32_t)hbits(v[2]) | ((uint32_t)hbits(v[3]) << 16);
        uint32_t off = swz((uint32_t)(n * 128 + kk0 * 2));
        *(uint2*)(dh + off) = ph;
    }
}

__global__ void a_limbs_kernel(const float* __restrict__ inp) {
    const int blk = blockIdx.x;            // rt*6 + kc
    const int rt = blk / NCHUNK, kc = blk % NCHUNK;
    const int i = rt >> 2;
    const int tid = threadIdx.x;
    const int kk0 = (tid & 15) * 4;
    char* dh = (char*)g_Ah + (size_t)blk * AB_BLK;
    for (int it = 0; it < 8; it++) {
        int row = it * 16 + (tid >> 4);
        int r = (rt & 3) * 128 + row;
        float v[4];
        if (kc < 2) {
            float4 f4 = *(const float4*)&inp[r * 1024 + i * 128 + kc * 64 + kk0];
            v[0] = f4.x; v[1] = f4.y; v[2] = f4.z; v[3] = f4.w;
        } else if (i == 0) {
            v[0] = v[1] = v[2] = v[3] = 0.f;
        } else {
            float4 f4 = *(const float4*)&g_H[(size_t)((i - 1) * 512 + r) * 256 +
                                             (kc - 2) * 64 + kk0];
            v[0] = f4.x; v[1] = f4.y; v[2] = f4.z; v[3] = f4.w;
        }
        uint2 ph;
        ph.x = (uint32_t)hbits(v[0]) | ((uint32_t)hbits(v[1]) << 16);
        ph.y = (uint32_t)hbits(v[2]) | ((uint32_t)hbits(v[3]) << 16);
        uint32_t off = swz((uint32_t)(row * 128 + kk0 * 2));
        *(uint2*)(dh + off) = ph;
    }
}

// ---------------------------------------------------------------------------
// Main GEMM (unchanged — passing since round 8)
// ---------------------------------------------------------------------------
__global__ __launch_bounds__(512, 1) void main_mma_kernel(float* __restrict__ out) {
    extern __shared__ char smem[];
    const uint32_t sb = smem_u32(smem);
    const int tid = threadIdx.x;
    const int wid = tid >> 5;
    const int lane = tid & 31;
    const int t = blockIdx.x;
    const int by = blockIdx.y;

    const int m0w = (wid & 3) * 32;
    const int n0w = (wid >> 2) * 64;

    int clist[6] = {0, 1, 2, 3, 4, 5};
    int nch = 6;
    if (t < 64) { clist[1] = 2; clist[2] = 3; clist[3] = 4; clist[4] = 5; nch = 5; }

    const int nks_c0 = min(4, (t >> 4) + 1);
    const int nks_c1 = (t < 64) ? 0 : min(4, ((t - 64) >> 4) + 1);

    const char* Asrc = (const char*)g_Ah + (size_t)by * NCHUNK * AB_BLK;
    const char* Bsrc = (const char*)g_Bh + (size_t)t * NCHUNK * BB_BLK;

    const uint32_t cpo = (uint32_t)tid * 16;

    uint32_t aoff[2][4];
    uint32_t boff[4][4];
    {
        const uint32_t arow = (uint32_t)(m0w + (lane & 15)) * 128;
        const uint32_t khalf = (uint32_t)(lane >> 4) * 16;
#pragma unroll
        for (int mt = 0; mt < 2; mt++)
#pragma unroll
            for (int ks = 0; ks < 4; ks++)
                aoff[mt][ks] = swz(arow + (uint32_t)mt * 2048 + khalf + ks * 32);
        const uint32_t brow = (uint32_t)(n0w + (lane & 15)) * 128;
#pragma unroll
        for (int ng = 0; ng < 4; ng++)
#pragma unroll
            for (int ks = 0; ks < 4; ks++)
                boff[ng][ks] = swz(brow + (uint32_t)ng * 2048 + khalf + ks * 32);
    }

    float acc[2][8][4];
#pragma unroll
    for (int mt = 0; mt < 2; mt++)
#pragma unroll
        for (int nt = 0; nt < 8; nt++)
#pragma unroll
            for (int q = 0; q < 4; q++) acc[mt][nt][q] = 0.f;

#define LOAD_STAGE(kc, st)                                                      \
    do {                                                                        \
        uint32_t s0 = sb + (uint32_t)(st) * ST_SZ;                              \
        const char* ga = Asrc + (size_t)(kc) * AB_BLK;                          \
        const char* gc = Bsrc + (size_t)(kc) * BB_BLK;                          \
        cp16(s0 + cpo, ga + cpo);                                               \
        cp16(s0 + 8192 + cpo, ga + 8192 + cpo);                                 \
        _Pragma("unroll")                                                       \
        for (int q = 0; q < 4; q++)                                             \
            cp16(s0 + ST_B + q * 8192 + cpo, gc + q * 8192 + cpo);              \
        CP_COMMIT();                                                            \
    } while (0)

    LOAD_STAGE(clist[0], 0);
    LOAD_STAGE(clist[1], 1);

    for (int j = 0; j < nch; j++) {
        if (j + NSTG - 1 < nch) {
            LOAD_STAGE(clist[j + NSTG - 1], (j + NSTG - 1) % NSTG);
            CP_WAIT(2);
        } else if (j == nch - 2) {
            CP_WAIT(1);
        } else {
            CP_WAIT(0);
        }
        __syncthreads();
        const uint32_t st = sb + (uint32_t)(j % NSTG) * ST_SZ;
        const int kc = clist[j];
        const int nks = (kc == 0) ? nks_c0 : ((kc == 1) ? nks_c1 : 4);
#pragma unroll
        for (int ks = 0; ks < 4; ks++) {
            if (ks >= nks) break;
            uint32_t ah[2][4];
            ldm4(ah[0], st + aoff[0][ks]);
            ldm4(ah[1], st + aoff[1][ks]);
#pragma unroll
            for (int ng = 0; ng < 4; ng++) {
                uint32_t bh[4];
                ldm4(bh, st + ST_B + boff[ng][ks]);
#pragma unroll
                for (int mt = 0; mt < 2; mt++) {
                    mma16816(acc[mt][2 * ng + 0], ah[mt], bh[0], bh[2]);
                    mma16816(acc[mt][2 * ng + 1], ah[mt], bh[1], bh[3]);
                }
            }
        }
        __syncthreads();
    }
#undef LOAD_STAGE

    const int i_ch = by >> 2;
    float* ob = out + (size_t)(i_ch * 128 + t) * 131072;
    const int rbase = (by & 3) * 128 + m0w + (lane >> 2);
    const int cbase = n0w + (lane & 3) * 2;
#pragma unroll
    for (int mt = 0; mt < 2; mt++) {
        const int r0 = rbase + mt * 16;
#pragma unroll
        for (int nt = 0; nt < 8; nt++) {
            const int c = cbase + nt * 8;
            float2 v0 = make_float2(acc[mt][nt][0], acc[mt][nt][1]);
            float2 v1 = make_float2(acc[mt][nt][2], acc[mt][nt][3]);
            __stcs((float2*)(ob + (size_t)r0 * 256 + c), v0);
            __stcs((float2*)(ob + (size_t)(r0 + 8) * 256 + c), v1);
        }
    }
}

// ---------------------------------------------------------------------------
extern "C" void kernel_launch(void* const* d_in, const int* in_sizes, int n_in,
                              void* d_out, int out_size) {
    const float* inp = (const float*)d_in[0];   // (8,64,1024)
    const float* A   = (const float*)d_in[1];   // (256,256)
    const float* Bv  = (const float*)d_in[2];   // (256,)
    float* out = (float*)d_out;

    cudaFuncSetAttribute(main_mma_kernel,
                         cudaFuncAttributeMaxDynamicSharedMemorySize, SMEM_SZ);
    cudaFuncSetAttribute(pow_mma_kernel,
                         cudaFuncAttributeMaxDynamicSharedMemorySize, PW_SMEM);

    conv_a_kernel<<<64, 256>>>(A);
    for (int d = 1; d <= 64; d <<= 1)
        pow_mma_kernel<<<dim3(2, 2, d), 256, PW_SMEM>>>(d);

    v_kernel<<<128, 256>>>(Bv);
    b_limbs_kernel<<<128 * NCHUNK, 256>>>();
    s_kernel<<<dim3(512, 8), 256>>>(inp);

    // stride-2 Horner: T + Q2, then pairs (H2,H3), (H4,H5), (H6)
    tprep_kernel<<<832, 256>>>();
    pair_kernel<<<256, 256>>>(1);
    pair_kernel<<<256, 256>>>(2);
    pair_kernel<<<128, 256>>>(3);

    a_limbs_kernel<<<32 * NCHUNK, 256>>>(inp);

    main_mma_kernel<<<dim3(128, 32), 512, SMEM_SZ>>>(out);
}